// round 2
// baseline (speedup 1.0000x reference)
#include <cuda_runtime.h>
#include <math.h>

#define B 8
#define L 2048
#define NT 21          // num types incl. padding idx 0
#define DTY 32
#define DH 544         // 512 + 32
#define TILE_I 8
#define THREADS 256

// 21x21 table: {0.4*g, 0.3*g, 1/l, 1/(2l^2)} indexed [type_i*NT + type_j]
__device__ float4 g_tab[NT * NT];

// ---------------------------------------------------------------------------
// Kernel 1: build the (type_i, type_j) table. 441 entries, trivially cheap.
// ---------------------------------------------------------------------------
__global__ void build_tables(const float* __restrict__ type_emb,
                             const float* __restrict__ w_l, const float* __restrict__ b_l,
                             const float* __restrict__ w_g, const float* __restrict__ b_g) {
    __shared__ float pa[NT], pb[NT], ga[NT], gb[NT];
    int t = threadIdx.x;
    if (t < NT) {
        float sa = 0.f, sb = 0.f, sga = 0.f, sgb = 0.f;
#pragma unroll
        for (int k = 0; k < DTY; k++) {
            float e = type_emb[t * DTY + k];
            sa  = fmaf(e, w_l[k],        sa);
            sb  = fmaf(e, w_l[DTY + k],  sb);
            sga = fmaf(e, w_g[k],        sga);
            sgb = fmaf(e, w_g[DTY + k],  sgb);
        }
        pa[t] = sa; pb[t] = sb; ga[t] = sga; gb[t] = sgb;
    }
    __syncthreads();
    float blv = b_l[0], bgv = b_g[0];
    for (int idx = threadIdx.x; idx < NT * NT; idx += blockDim.x) {
        int ti = idx / NT;   // i-side type
        int tj = idx % NT;   // j-side type
        // l = softplus(pa[j] + pb[i] + b_l) + eps   (stable softplus)
        float xl = pa[tj] + pb[ti] + blv;
        float sp = fmaxf(xl, 0.f) + log1pf(expf(-fabsf(xl)));
        float lv = sp + 1e-6f;
        // g = sigmoid(5 * (ga[j] + gb[i] + b_g))
        float xg = 5.0f * (ga[tj] + gb[ti] + bgv);
        float g  = 1.f / (1.f + expf(-xg));
        float4 v;
        v.x = 0.4f * g;
        v.y = 0.3f * g;
        v.z = 1.f / lv;
        v.w = 1.f / (2.f * lv * lv);
        g_tab[idx] = v;
    }
}

// ---------------------------------------------------------------------------
// Kernel 2: hidden_vector [B, L, 544] = concat(sin(arc+phi), cos(arc+phi), te)
// One block per (b, l); thread k handles frequency k.
// ---------------------------------------------------------------------------
__global__ __launch_bounds__(256) void hidden_kernel(
    const int* __restrict__ event_type, const float* __restrict__ event_time,
    const float* __restrict__ Wt_pos, const float* __restrict__ type_emb,
    float* __restrict__ hidden) {
    int bl = blockIdx.x;          // 0 .. B*L-1
    int l  = bl % L;
    int k  = threadIdx.x;         // 0 .. 255
    float tval = event_time[bl];
    // div_term[k] = exp(2k * (-ln(10000)/512))
    const float c = (float)(-9.210340371976184 / 512.0);   // -ln(10000)/D_MODEL
    float div = expf((float)(2 * k) * c);
    float arc = (float)l * div;
    float phi = tval * Wt_pos[k];
    float s, cth;
    sincosf(arc + phi, &s, &cth);
    float* base = hidden + (size_t)bl * DH;
    base[k]       = s;
    base[256 + k] = cth;
    if (k < DTY) {
        int ty = event_type[bl];
        base[512 + k] = type_emb[ty * DTY + k];
    }
}

// ---------------------------------------------------------------------------
// Kernel 3: pairwise scores + t_diff. Each block owns TILE_I=8 rows of one
// batch. t-row, type-row, and the full 441-entry table live in smem; HBM
// traffic is essentially only the streaming float4 stores.
// ---------------------------------------------------------------------------
__global__ __launch_bounds__(THREADS) void pairwise_kernel(
    const int* __restrict__ event_type, const float* __restrict__ event_time,
    float* __restrict__ scores, float* __restrict__ tdiff) {
    __shared__ float          s_t[L];
    __shared__ unsigned char  s_ty[L];
    __shared__ float4         s_tab[NT * NT];

    int blk = blockIdx.x;
    int b   = blk / (L / TILE_I);
    int i0  = (blk % (L / TILE_I)) * TILE_I;

    for (int j = threadIdx.x; j < L; j += THREADS) {
        s_t[j]  = event_time[b * L + j];
        s_ty[j] = (unsigned char)event_type[b * L + j];
    }
    for (int idx = threadIdx.x; idx < NT * NT; idx += THREADS)
        s_tab[idx] = g_tab[idx];
    __syncthreads();

#pragma unroll
    for (int ii = 0; ii < TILE_I; ii++) {
        int   i       = i0 + ii;
        float ti      = s_t[i];
        int   tabbase = (int)s_ty[i] * NT;
        size_t rowbase = ((size_t)(b * L + i)) * L;
#pragma unroll
        for (int jj = 0; jj < L; jj += THREADS * 4) {
            int j = jj + threadIdx.x * 4;
            float4 tj  = *reinterpret_cast<const float4*>(&s_t[j]);
            uchar4 ty4 = *reinterpret_cast<const uchar4*>(&s_ty[j]);
            float4 dv, sv;
            {
                float d = fabsf(ti - tj.x);
                float4 v = s_tab[tabbase + ty4.x];
                float se = __expf(-d * d * v.w);
                float ex = __expf(-d * v.z);
                dv.x = d;
                sv.x = (j + 0 < i) ? fmaf(v.x, se, v.y * ex) : 0.f;
            }
            {
                float d = fabsf(ti - tj.y);
                float4 v = s_tab[tabbase + ty4.y];
                float se = __expf(-d * d * v.w);
                float ex = __expf(-d * v.z);
                dv.y = d;
                sv.y = (j + 1 < i) ? fmaf(v.x, se, v.y * ex) : 0.f;
            }
            {
                float d = fabsf(ti - tj.z);
                float4 v = s_tab[tabbase + ty4.z];
                float se = __expf(-d * d * v.w);
                float ex = __expf(-d * v.z);
                dv.z = d;
                sv.z = (j + 2 < i) ? fmaf(v.x, se, v.y * ex) : 0.f;
            }
            {
                float d = fabsf(ti - tj.w);
                float4 v = s_tab[tabbase + ty4.w];
                float se = __expf(-d * d * v.w);
                float ex = __expf(-d * v.z);
                dv.w = d;
                sv.w = (j + 3 < i) ? fmaf(v.x, se, v.y * ex) : 0.f;
            }
            *reinterpret_cast<float4*>(&scores[rowbase + j]) = sv;
            *reinterpret_cast<float4*>(&tdiff[rowbase + j])  = dv;
        }
    }
}

// ---------------------------------------------------------------------------
// Launch: tables -> hidden -> pairwise (same stream, graph-capturable,
// no allocations; scratch table lives in a __device__ global).
// ---------------------------------------------------------------------------
extern "C" void kernel_launch(void* const* d_in, const int* in_sizes, int n_in,
                              void* d_out, int out_size) {
    const int*   event_type = (const int*)d_in[0];
    const float* event_time = (const float*)d_in[1];
    // d_in[2] = arrival_times (unused by reference)
    const float* Wt_pos   = (const float*)d_in[3];
    const float* type_emb = (const float*)d_in[4];
    const float* w_l      = (const float*)d_in[5];
    const float* b_l      = (const float*)d_in[6];
    const float* w_g      = (const float*)d_in[7];
    const float* b_g      = (const float*)d_in[8];

    float* out    = (float*)d_out;
    float* scores = out;                                   // [B, L, L]
    float* hidden = out + (size_t)B * L * L;               // [B, L, 544]
    float* tdiff  = hidden + (size_t)B * L * DH;           // [B, L, L]

    build_tables<<<1, 448>>>(type_emb, w_l, b_l, w_g, b_g);
    hidden_kernel<<<B * L, 256>>>(event_type, event_time, Wt_pos, type_emb, hidden);
    pairwise_kernel<<<(B * L) / TILE_I, THREADS>>>(event_type, event_time, scores, tdiff);
}

// round 4
// speedup vs baseline: 1.1197x; 1.1197x over previous
#include <cuda_runtime.h>
#include <math.h>

#define B 8
#define L 2048
#define NT 21          // num types incl. padding idx 0
#define DTY 32
#define DH 544         // 512 + 32
#define TILE_I 8
#define THREADS 256
#define BLOCKS_PER_B (L / TILE_I)   // 256

// ---------------------------------------------------------------------------
// Single fused kernel. Each block owns TILE_I=8 rows (i-positions) of one
// batch. It:
//   1. loads t-row + type-row of its batch into smem,
//   2. builds the full 441-entry (type_i,type_j) coefficient table in smem
//      (redundantly per block -- 2048-way parallel, so effectively free),
//   3. writes the hidden_vector rows for its 8 positions,
//   4. streams the scores + t_diff rows as float4 stores.
// All 304 MB of output from one launch: no serial table/hidden kernels.
// ---------------------------------------------------------------------------
__global__ __launch_bounds__(THREADS) void fused_kernel(
    const int*   __restrict__ event_type,
    const float* __restrict__ event_time,
    const float* __restrict__ Wt_pos,
    const float* __restrict__ type_emb,
    const float* __restrict__ w_l, const float* __restrict__ b_l,
    const float* __restrict__ w_g, const float* __restrict__ b_g,
    float* __restrict__ scores,
    float* __restrict__ hidden,
    float* __restrict__ tdiff) {

    __shared__ float          s_t[L];
    __shared__ unsigned char  s_ty[L];
    __shared__ float4         s_tab[NT * NT];
    __shared__ float          pa[NT], pb[NT], ga[NT], gb[NT];

    const int tid = threadIdx.x;
    const int blk = blockIdx.x;
    const int b   = blk / BLOCKS_PER_B;
    const int i0  = (blk % BLOCKS_PER_B) * TILE_I;

    // --- stage 1: row loads + per-type dot products -------------------------
    for (int j = tid; j < L; j += THREADS) {
        s_t[j]  = event_time[b * L + j];
        s_ty[j] = (unsigned char)event_type[b * L + j];
    }
    if (tid < NT) {
        float sa = 0.f, sb = 0.f, sga = 0.f, sgb = 0.f;
#pragma unroll
        for (int k = 0; k < DTY; k++) {
            float e = type_emb[tid * DTY + k];
            sa  = fmaf(e, w_l[k],       sa);
            sb  = fmaf(e, w_l[DTY + k], sb);
            sga = fmaf(e, w_g[k],       sga);
            sgb = fmaf(e, w_g[DTY + k], sgb);
        }
        pa[tid] = sa; pb[tid] = sb; ga[tid] = sga; gb[tid] = sgb;
    }
    __syncthreads();

    // --- stage 2: build 441-entry table (2 entries/thread) ------------------
    {
        const float blv = b_l[0], bgv = b_g[0];
        for (int idx = tid; idx < NT * NT; idx += THREADS) {
            int ti = idx / NT;   // i-side type
            int tj = idx % NT;   // j-side type
            float xl = pa[tj] + pb[ti] + blv;
            float sp = fmaxf(xl, 0.f) + log1pf(expf(-fabsf(xl)));
            float lv = sp + 1e-6f;
            float xg = 5.0f * (ga[tj] + gb[ti] + bgv);
            float g  = 1.f / (1.f + expf(-xg));
            float4 v;
            v.x = 0.4f * g;
            v.y = 0.3f * g;
            v.z = 1.f / lv;
            v.w = 1.f / (2.f * lv * lv);
            s_tab[idx] = v;
        }
    }

    // --- stage 3: hidden rows for this block's 8 positions ------------------
    // thread k handles frequency k for all 8 rows (div_term computed once).
    {
        const float c   = (float)(-9.210340371976184 / 512.0); // -ln(10000)/d_model
        const float div = expf((float)(2 * tid) * c);
        const float wt  = Wt_pos[tid];
#pragma unroll
        for (int ii = 0; ii < TILE_I; ii++) {
            int   i    = i0 + ii;
            float tval = s_t[i];
            float s, cth;
            sincosf((float)i * div + tval * wt, &s, &cth);
            float* base = hidden + ((size_t)(b * L + i)) * DH;
            base[tid]       = s;
            base[256 + tid] = cth;
        }
        // type-embedding tail: 8 rows x 32 cols = 256 values, one per thread
        int row = tid >> 5;
        int col = tid & 31;
        int i   = i0 + row;
        int ty  = (int)s_ty[i];
        hidden[((size_t)(b * L + i)) * DH + 512 + col] = type_emb[ty * DTY + col];
    }
    __syncthreads();   // s_tab must be complete before pairwise reads

    // --- stage 4: stream pairwise scores + t_diff ---------------------------
#pragma unroll
    for (int ii = 0; ii < TILE_I; ii++) {
        const int    i       = i0 + ii;
        const float  ti      = s_t[i];
        const int    tabbase = (int)s_ty[i] * NT;
        const size_t rowbase = ((size_t)(b * L + i)) * L;
#pragma unroll
        for (int jj = 0; jj < L; jj += THREADS * 4) {
            int j = jj + tid * 4;
            float4 tj  = *reinterpret_cast<const float4*>(&s_t[j]);
            uchar4 ty4 = *reinterpret_cast<const uchar4*>(&s_ty[j]);
            float4 dv, sv;
            {
                float d = fabsf(ti - tj.x);
                float4 v = s_tab[tabbase + ty4.x];
                float se = __expf(-d * d * v.w);
                float ex = __expf(-d * v.z);
                dv.x = d;
                sv.x = (j + 0 < i) ? fmaf(v.x, se, v.y * ex) : 0.f;
            }
            {
                float d = fabsf(ti - tj.y);
                float4 v = s_tab[tabbase + ty4.y];
                float se = __expf(-d * d * v.w);
                float ex = __expf(-d * v.z);
                dv.y = d;
                sv.y = (j + 1 < i) ? fmaf(v.x, se, v.y * ex) : 0.f;
            }
            {
                float d = fabsf(ti - tj.z);
                float4 v = s_tab[tabbase + ty4.z];
                float se = __expf(-d * d * v.w);
                float ex = __expf(-d * v.z);
                dv.z = d;
                sv.z = (j + 2 < i) ? fmaf(v.x, se, v.y * ex) : 0.f;
            }
            {
                float d = fabsf(ti - tj.w);
                float4 v = s_tab[tabbase + ty4.w];
                float se = __expf(-d * d * v.w);
                float ex = __expf(-d * v.z);
                dv.w = d;
                sv.w = (j + 3 < i) ? fmaf(v.x, se, v.y * ex) : 0.f;
            }
            *reinterpret_cast<float4*>(&scores[rowbase + j]) = sv;
            *reinterpret_cast<float4*>(&tdiff[rowbase + j])  = dv;
        }
    }
}

// ---------------------------------------------------------------------------
extern "C" void kernel_launch(void* const* d_in, const int* in_sizes, int n_in,
                              void* d_out, int out_size) {
    const int*   event_type = (const int*)d_in[0];
    const float* event_time = (const float*)d_in[1];
    // d_in[2] = arrival_times (unused by reference)
    const float* Wt_pos   = (const float*)d_in[3];
    const float* type_emb = (const float*)d_in[4];
    const float* w_l      = (const float*)d_in[5];
    const float* b_l      = (const float*)d_in[6];
    const float* w_g      = (const float*)d_in[7];
    const float* b_g      = (const float*)d_in[8];

    float* out    = (float*)d_out;
    float* scores = out;                                   // [B, L, L]
    float* hidden = out + (size_t)B * L * L;               // [B, L, 544]
    float* tdiff  = hidden + (size_t)B * L * DH;           // [B, L, L]

    fused_kernel<<<B * BLOCKS_PER_B, THREADS>>>(
        event_type, event_time, Wt_pos, type_emb,
        w_l, b_l, w_g, b_g, scores, hidden, tdiff);
}

// round 6
// speedup vs baseline: 1.2072x; 1.0781x over previous
#include <cuda_runtime.h>
#include <math.h>

#define B 8
#define L 2048
#define NT 21          // num types incl. padding idx 0
#define DTY 32
#define DH 544         // 512 + 32
#define TILE_I 8
#define THREADS 256
#define BLOCKS_PER_B (L / TILE_I)   // 256

// ---------------------------------------------------------------------------
// Single fused kernel, one wave of 2048 blocks writes all 304 MB of output.
// Table entries reduced to float2 {0.4*g, 1/l}:
//   e   = d / l
//   se  = exp(-0.5*e*e)          (== exp(-d^2/(2 l^2)))
//   ex  = exp(-e)                (== exp(-d/l))
//   score = 0.4g*se + 0.3g*ex = (0.4g) * (se + 0.75*ex)
// Upper-triangle (j >= i) skips the table lookup + both exps entirely.
// ---------------------------------------------------------------------------
__global__ __launch_bounds__(THREADS) void fused_kernel(
    const int*   __restrict__ event_type,
    const float* __restrict__ event_time,
    const float* __restrict__ Wt_pos,
    const float* __restrict__ type_emb,
    const float* __restrict__ w_l, const float* __restrict__ b_l,
    const float* __restrict__ w_g, const float* __restrict__ b_g,
    float* __restrict__ scores,
    float* __restrict__ hidden,
    float* __restrict__ tdiff) {

    __shared__ float          s_t[L];
    __shared__ unsigned char  s_ty[L];
    __shared__ float2         s_tab[NT * NT];
    __shared__ float          pa[NT], pb[NT], ga[NT], gb[NT];

    const int tid = threadIdx.x;
    const int blk = blockIdx.x;
    const int b   = blk / BLOCKS_PER_B;
    const int i0  = (blk % BLOCKS_PER_B) * TILE_I;

    // --- stage 1: row loads + per-type dot products -------------------------
    for (int j = tid; j < L; j += THREADS) {
        s_t[j]  = event_time[b * L + j];
        s_ty[j] = (unsigned char)event_type[b * L + j];
    }
    if (tid < NT) {
        float sa = 0.f, sb = 0.f, sga = 0.f, sgb = 0.f;
#pragma unroll
        for (int k = 0; k < DTY; k++) {
            float e = type_emb[tid * DTY + k];
            sa  = fmaf(e, w_l[k],       sa);
            sb  = fmaf(e, w_l[DTY + k], sb);
            sga = fmaf(e, w_g[k],       sga);
            sgb = fmaf(e, w_g[DTY + k], sgb);
        }
        pa[tid] = sa; pb[tid] = sb; ga[tid] = sga; gb[tid] = sgb;
    }
    __syncthreads();

    // --- stage 2: build 441-entry float2 table ------------------------------
    {
        const float blv = b_l[0], bgv = b_g[0];
        for (int idx = tid; idx < NT * NT; idx += THREADS) {
            int ti = idx / NT;   // i-side type
            int tj = idx % NT;   // j-side type
            float xl = pa[tj] + pb[ti] + blv;
            float sp = fmaxf(xl, 0.f) + log1pf(expf(-fabsf(xl)));
            float lv = sp + 1e-6f;
            float xg = 5.0f * (ga[tj] + gb[ti] + bgv);
            float g  = 1.f / (1.f + expf(-xg));
            s_tab[idx] = make_float2(0.4f * g, 1.f / lv);
        }
    }

    // --- stage 3: hidden rows for this block's 8 positions ------------------
    {
        const float c   = (float)(-9.210340371976184 / 512.0); // -ln(10000)/d_model
        const float div = expf((float)(2 * tid) * c);
        const float wt  = Wt_pos[tid];
#pragma unroll
        for (int ii = 0; ii < TILE_I; ii++) {
            int   i    = i0 + ii;
            float tval = s_t[i];
            float s, cth;
            sincosf((float)i * div + tval * wt, &s, &cth);
            float* base = hidden + ((size_t)(b * L + i)) * DH;
            base[tid]       = s;
            base[256 + tid] = cth;
        }
        int row = tid >> 5;
        int col = tid & 31;
        int i   = i0 + row;
        int ty  = (int)s_ty[i];
        hidden[((size_t)(b * L + i)) * DH + 512 + col] = type_emb[ty * DTY + col];
    }
    __syncthreads();   // s_tab must be complete before pairwise reads

    // --- stage 4: stream pairwise scores + t_diff ---------------------------
#pragma unroll
    for (int ii = 0; ii < TILE_I; ii++) {
        const int    i       = i0 + ii;
        const float  ti      = s_t[i];
        const int    tabbase = (int)s_ty[i] * NT;
        const size_t rowbase = ((size_t)(b * L + i)) * L;
#pragma unroll
        for (int jj = 0; jj < L; jj += THREADS * 4) {
            const int j = jj + tid * 4;
            float4 tj = *reinterpret_cast<const float4*>(&s_t[j]);
            float4 dv;
            dv.x = fabsf(ti - tj.x);
            dv.y = fabsf(ti - tj.y);
            dv.z = fabsf(ti - tj.z);
            dv.w = fabsf(ti - tj.w);

            float4 sv;
            if (j >= i) {
                // strictly upper triangle: score == 0, skip all table/exp work
                sv = make_float4(0.f, 0.f, 0.f, 0.f);
            } else {
                uchar4 ty4 = *reinterpret_cast<const uchar4*>(&s_ty[j]);
                {
                    float2 v = s_tab[tabbase + ty4.x];
                    float  e = dv.x * v.y;
                    float se = __expf(-0.5f * e * e);
                    float ex = __expf(-e);
                    sv.x = (j + 0 < i) ? v.x * fmaf(0.75f, ex, se) : 0.f;
                }
                {
                    float2 v = s_tab[tabbase + ty4.y];
                    float  e = dv.y * v.y;
                    float se = __expf(-0.5f * e * e);
                    float ex = __expf(-e);
                    sv.y = (j + 1 < i) ? v.x * fmaf(0.75f, ex, se) : 0.f;
                }
                {
                    float2 v = s_tab[tabbase + ty4.z];
                    float  e = dv.z * v.y;
                    float se = __expf(-0.5f * e * e);
                    float ex = __expf(-e);
                    sv.z = (j + 2 < i) ? v.x * fmaf(0.75f, ex, se) : 0.f;
                }
                {
                    float2 v = s_tab[tabbase + ty4.w];
                    float  e = dv.w * v.y;
                    float se = __expf(-0.5f * e * e);
                    float ex = __expf(-e);
                    sv.w = (j + 3 < i) ? v.x * fmaf(0.75f, ex, se) : 0.f;
                }
            }
            *reinterpret_cast<float4*>(&scores[rowbase + j]) = sv;
            *reinterpret_cast<float4*>(&tdiff[rowbase + j])  = dv;
        }
    }
}

// ---------------------------------------------------------------------------
extern "C" void kernel_launch(void* const* d_in, const int* in_sizes, int n_in,
                              void* d_out, int out_size) {
    const int*   event_type = (const int*)d_in[0];
    const float* event_time = (const float*)d_in[1];
    // d_in[2] = arrival_times (unused by reference)
    const float* Wt_pos   = (const float*)d_in[3];
    const float* type_emb = (const float*)d_in[4];
    const float* w_l      = (const float*)d_in[5];
    const float* b_l      = (const float*)d_in[6];
    const float* w_g      = (const float*)d_in[7];
    const float* b_g      = (const float*)d_in[8];

    float* out    = (float*)d_out;
    float* scores = out;                                   // [B, L, L]
    float* hidden = out + (size_t)B * L * L;               // [B, L, 544]
    float* tdiff  = hidden + (size_t)B * L * DH;           // [B, L, L]

    fused_kernel<<<B * BLOCKS_PER_B, THREADS>>>(
        event_type, event_time, Wt_pos, type_emb,
        w_l, b_l, w_g, b_g, scores, hidden, tdiff);
}

// round 7
// speedup vs baseline: 1.2826x; 1.0625x over previous
#include <cuda_runtime.h>
#include <math.h>

#define B 8
#define L 2048
#define NT 21          // num types incl. padding idx 0
#define DTY 32
#define DH 544         // 512 + 32
#define THREADS 256
#define QBLK 256       // row-pair tiles per batch (each owns 8 rows)

// ---------------------------------------------------------------------------
// Single fused kernel. Block q of batch b owns mirrored rows
//   {4q..4q+3}  and  {L-4-4q .. L-1-4q}
// so every block performs exactly half-triangle exp/table work (no straggler
// blocks). Inner loop is j-outer: the j-side time/type loads are shared
// across all 8 rows. All outputs stored with streaming hint (__stcs).
// ---------------------------------------------------------------------------
__global__ __launch_bounds__(THREADS, 6) void fused_kernel(
    const int*   __restrict__ event_type,
    const float* __restrict__ event_time,
    const float* __restrict__ Wt_pos,
    const float* __restrict__ type_emb,
    const float* __restrict__ w_l, const float* __restrict__ b_l,
    const float* __restrict__ w_g, const float* __restrict__ b_g,
    float* __restrict__ scores,
    float* __restrict__ hidden,
    float* __restrict__ tdiff) {

    __shared__ float          s_t[L];
    __shared__ unsigned char  s_ty[L];
    __shared__ float2         s_tab[NT * NT];   // [ty_i * NT + ty_j] = {0.4g, 1/l}
    __shared__ float          pa[NT], pb[NT], ga[NT], gb[NT];

    const int tid = threadIdx.x;
    const int blk = blockIdx.x;
    const int b   = blk / QBLK;
    const int q   = blk % QBLK;
    const int q4  = q * 4;
    const int mir = L - 4 - q4;          // base of mirrored 4-row group

    // --- stage 1: row loads + per-type dot products -------------------------
    for (int j = tid; j < L; j += THREADS) {
        s_t[j]  = event_time[b * L + j];
        s_ty[j] = (unsigned char)event_type[b * L + j];
    }
    if (tid < NT) {
        float sa = 0.f, sb = 0.f, sga = 0.f, sgb = 0.f;
#pragma unroll
        for (int k = 0; k < DTY; k++) {
            float e = type_emb[tid * DTY + k];
            sa  = fmaf(e, w_l[k],       sa);
            sb  = fmaf(e, w_l[DTY + k], sb);
            sga = fmaf(e, w_g[k],       sga);
            sgb = fmaf(e, w_g[DTY + k], sgb);
        }
        pa[tid] = sa; pb[tid] = sb; ga[tid] = sga; gb[tid] = sgb;
    }
    __syncthreads();

    // --- stage 2: build 441-entry float2 table ------------------------------
    {
        const float blv = b_l[0], bgv = b_g[0];
        for (int idx = tid; idx < NT * NT; idx += THREADS) {
            int ti = idx / NT;   // i-side type
            int tj = idx % NT;   // j-side type
            float xl = pa[tj] + pb[ti] + blv;
            float sp = fmaxf(xl, 0.f) + log1pf(expf(-fabsf(xl)));
            float lv = sp + 1e-6f;
            float xg = 5.0f * (ga[tj] + gb[ti] + bgv);
            float g  = 1.f / (1.f + expf(-xg));
            s_tab[idx] = make_float2(0.4f * g, 1.f / lv);
        }
    }

    // --- stage 3: hidden rows for this block's 8 (mirrored) positions -------
    {
        const float c   = (float)(-9.210340371976184 / 512.0); // -ln(10000)/d_model
        const float div = expf((float)(2 * tid) * c);
        const float wt  = Wt_pos[tid];
#pragma unroll
        for (int ii = 0; ii < 8; ii++) {
            int   i    = (ii < 4) ? (q4 + ii) : (mir + ii - 4);
            float tval = s_t[i];
            float s, cth;
            sincosf((float)i * div + tval * wt, &s, &cth);
            float* base = hidden + ((size_t)(b * L + i)) * DH;
            __stcs(base + tid,       s);
            __stcs(base + 256 + tid, cth);
        }
        int row = tid >> 5;                 // 0..7 -> one of the 8 rows
        int col = tid & 31;
        int i   = (row < 4) ? (q4 + row) : (mir + row - 4);
        int ty  = (int)s_ty[i];
        __stcs(hidden + ((size_t)(b * L + i)) * DH + 512 + col,
               type_emb[ty * DTY + col]);
    }
    __syncthreads();   // s_tab must be complete before pairwise reads

    // --- stage 4: stream pairwise scores + t_diff (j-outer, rows-inner) ----
    float ti_r[8];
    int   tb_r[8];
#pragma unroll
    for (int ii = 0; ii < 8; ii++) {
        int i = (ii < 4) ? (q4 + ii) : (mir + ii - 4);
        ti_r[ii] = s_t[i];
        tb_r[ii] = (int)s_ty[i] * NT;
    }
    float* sc0 = scores + ((size_t)(b * L + q4))  * L;
    float* td0 = tdiff  + ((size_t)(b * L + q4))  * L;
    float* sc1 = scores + ((size_t)(b * L + mir)) * L;
    float* td1 = tdiff  + ((size_t)(b * L + mir)) * L;

    for (int jj = 0; jj < L; jj += THREADS * 4) {
        const int j = jj + tid * 4;
        const float4 tj  = *reinterpret_cast<const float4*>(&s_t[j]);
        const uchar4 tyv = *reinterpret_cast<const uchar4*>(&s_ty[j]);
        const int jx = tyv.x, jy = tyv.y, jz = tyv.z, jw = tyv.w;

#pragma unroll
        for (int ii = 0; ii < 8; ii++) {
            const int   i  = (ii < 4) ? (q4 + ii) : (mir + ii - 4);
            const float ti = ti_r[ii];
            float4 dv;
            dv.x = fabsf(ti - tj.x);
            dv.y = fabsf(ti - tj.y);
            dv.z = fabsf(ti - tj.z);
            dv.w = fabsf(ti - tj.w);

            float4 sv = make_float4(0.f, 0.f, 0.f, 0.f);
            if (j < i) {                    // at least one lower-triangle elem
                const int tb = tb_r[ii];
                {
                    float2 v = s_tab[tb + jx];
                    float  e = dv.x * v.y;
                    float se = __expf(-0.5f * e * e);
                    float ex = __expf(-e);
                    sv.x = v.x * fmaf(0.75f, ex, se);
                }
                {
                    float2 v = s_tab[tb + jy];
                    float  e = dv.y * v.y;
                    float se = __expf(-0.5f * e * e);
                    float ex = __expf(-e);
                    sv.y = (j + 1 < i) ? v.x * fmaf(0.75f, ex, se) : 0.f;
                }
                {
                    float2 v = s_tab[tb + jz];
                    float  e = dv.z * v.y;
                    float se = __expf(-0.5f * e * e);
                    float ex = __expf(-e);
                    sv.z = (j + 2 < i) ? v.x * fmaf(0.75f, ex, se) : 0.f;
                }
                {
                    float2 v = s_tab[tb + jw];
                    float  e = dv.w * v.y;
                    float se = __expf(-0.5f * e * e);
                    float ex = __expf(-e);
                    sv.w = (j + 3 < i) ? v.x * fmaf(0.75f, ex, se) : 0.f;
                }
            }
            float* sc = (ii < 4) ? (sc0 + (size_t)ii * L) : (sc1 + (size_t)(ii - 4) * L);
            float* td = (ii < 4) ? (td0 + (size_t)ii * L) : (td1 + (size_t)(ii - 4) * L);
            __stcs(reinterpret_cast<float4*>(sc + j), sv);
            __stcs(reinterpret_cast<float4*>(td + j), dv);
        }
    }
}

// ---------------------------------------------------------------------------
extern "C" void kernel_launch(void* const* d_in, const int* in_sizes, int n_in,
                              void* d_out, int out_size) {
    const int*   event_type = (const int*)d_in[0];
    const float* event_time = (const float*)d_in[1];
    // d_in[2] = arrival_times (unused by reference)
    const float* Wt_pos   = (const float*)d_in[3];
    const float* type_emb = (const float*)d_in[4];
    const float* w_l      = (const float*)d_in[5];
    const float* b_l      = (const float*)d_in[6];
    const float* w_g      = (const float*)d_in[7];
    const float* b_g      = (const float*)d_in[8];

    float* out    = (float*)d_out;
    float* scores = out;                                   // [B, L, L]
    float* hidden = out + (size_t)B * L * L;               // [B, L, 544]
    float* tdiff  = hidden + (size_t)B * L * DH;           // [B, L, L]

    fused_kernel<<<B * QBLK, THREADS>>>(
        event_type, event_time, Wt_pos, type_emb,
        w_l, b_l, w_g, b_g, scores, hidden, tdiff);
}